// round 4
// baseline (speedup 1.0000x reference)
#include <cuda_runtime.h>

// Problem constants (fixed by the reference: B=32, d=512, T=2048)
#define B_  32
#define D_  512
#define T_  2048
#define FG  (4 * D_)        // 2048 G feature rows
#define FM  D_              // 512 m feature rows
#define FT  (FG + FM)       // 2560 total features
#define NSLICE 2
#define FS  (FT / NSLICE)   // 1280 features per slice
#define TILE_T 512
#define THREADS 128         // each thread handles 4 consecutive t (float4)

// Partial dot-product scratch: [slice][b][t] for each of the two heads. 1 MB total.
__device__ float g_part1[NSLICE * B_ * T_];
__device__ float g_part2[NSLICE * B_ * T_];

__global__ __launch_bounds__(THREADS)
void dot_kernel(const float* __restrict__ G,
                const float* __restrict__ m1,
                const float* __restrict__ m2,
                const float* __restrict__ wp1,
                const float* __restrict__ wp2) {
    __shared__ float w1s[FS];
    __shared__ float w2s[FS];

    const int b     = blockIdx.y;
    const int slice = blockIdx.z;
    const int fbase = slice * FS;

    // Stage this slice's weights in shared memory (10 KB)
    for (int i = threadIdx.x; i < FS; i += THREADS) {
        w1s[i] = wp1[fbase + i];
        w2s[i] = wp2[fbase + i];
    }
    __syncthreads();

    const int t0 = blockIdx.x * TILE_T + threadIdx.x * 4;

    float a1x = 0.f, a1y = 0.f, a1z = 0.f, a1w = 0.f;
    float a2x = 0.f, a2y = 0.f, a2z = 0.f, a2w = 0.f;

    // --- G portion of this slice: f in [fbase, min(fbase+FS, FG)) ---
    const int fG_end = (fbase + FS < FG) ? (fbase + FS) : FG;
    const float* Gb = G + (size_t)b * FG * T_ + t0;
#pragma unroll 8
    for (int f = fbase; f < fG_end; ++f) {
        float4 g = *(const float4*)(Gb + (size_t)f * T_);
        float w1 = w1s[f - fbase];
        float w2 = w2s[f - fbase];
        a1x = fmaf(g.x, w1, a1x);  a2x = fmaf(g.x, w2, a2x);
        a1y = fmaf(g.y, w1, a1y);  a2y = fmaf(g.y, w2, a2y);
        a1z = fmaf(g.z, w1, a1z);  a2z = fmaf(g.z, w2, a2z);
        a1w = fmaf(g.w, w1, a1w);  a2w = fmaf(g.w, w2, a2w);
    }

    // --- m portion of this slice: f in [max(fbase, FG), fbase+FS) ---
    const int fM_beg = (fbase > FG) ? fbase : FG;
    const int fM_end = fbase + FS;
    const float* M1b = m1 + (size_t)b * FM * T_ + t0;
    const float* M2b = m2 + (size_t)b * FM * T_ + t0;
#pragma unroll 8
    for (int f = fM_beg; f < fM_end; ++f) {
        const int fm = f - FG;
        float4 v1 = *(const float4*)(M1b + (size_t)fm * T_);
        float4 v2 = *(const float4*)(M2b + (size_t)fm * T_);
        float w1 = w1s[f - fbase];
        float w2 = w2s[f - fbase];
        a1x = fmaf(v1.x, w1, a1x);  a2x = fmaf(v2.x, w2, a2x);
        a1y = fmaf(v1.y, w1, a1y);  a2y = fmaf(v2.y, w2, a2y);
        a1z = fmaf(v1.z, w1, a1z);  a2z = fmaf(v2.z, w2, a2z);
        a1w = fmaf(v1.w, w1, a1w);  a2w = fmaf(v2.w, w2, a2w);
    }

    const int o = (slice * B_ + b) * T_ + t0;
    *(float4*)&g_part1[o] = make_float4(a1x, a1y, a1z, a1w);
    *(float4*)&g_part2[o] = make_float4(a2x, a2y, a2z, a2w);
}

// Softmax over T for each (b, head). grid = (2 heads, B), 256 threads; each
// thread owns 8 t-values (stride-256 for coalescing). Sums the two f-slice
// partials on load.
__global__ __launch_bounds__(256)
void softmax_kernel(float* __restrict__ out) {
    const int head = blockIdx.x;
    const int b    = blockIdx.y;
    const float* P = (head == 0) ? g_part1 : g_part2;
    const int tid  = threadIdx.x;

    float p[8];
    float mx = -3.402823466e+38f;
#pragma unroll
    for (int i = 0; i < 8; ++i) {
        const int t = i * 256 + tid;
        float v = P[b * T_ + t] + P[(B_ + b) * T_ + t];  // slice0 + slice1
        p[i] = v;
        mx = fmaxf(mx, v);
    }

    __shared__ float red[256];
    red[tid] = mx;
    __syncthreads();
#pragma unroll
    for (int s = 128; s > 0; s >>= 1) {
        if (tid < s) red[tid] = fmaxf(red[tid], red[tid + s]);
        __syncthreads();
    }
    mx = red[0];
    __syncthreads();

    float sum = 0.f;
#pragma unroll
    for (int i = 0; i < 8; ++i) {
        p[i] = __expf(p[i] - mx);
        sum += p[i];
    }
    red[tid] = sum;
    __syncthreads();
#pragma unroll
    for (int s = 128; s > 0; s >>= 1) {
        if (tid < s) red[tid] += red[tid + s];
        __syncthreads();
    }
    const float inv = 1.0f / red[0];

#pragma unroll
    for (int i = 0; i < 8; ++i) {
        const int t = i * 256 + tid;
        out[((size_t)b * 2 + head) * T_ + t] = p[i] * inv;
    }
}

extern "C" void kernel_launch(void* const* d_in, const int* in_sizes, int n_in,
                              void* d_out, int out_size) {
    const float* G   = (const float*)d_in[0];
    const float* m1  = (const float*)d_in[1];
    const float* m2  = (const float*)d_in[2];
    const float* wp1 = (const float*)d_in[3];
    const float* wp2 = (const float*)d_in[4];
    float* out = (float*)d_out;

    dim3 grid(T_ / TILE_T, B_, NSLICE);   // (4, 32, 2) = 256 blocks
    dot_kernel<<<grid, THREADS>>>(G, m1, m2, wp1, wp2);

    softmax_kernel<<<dim3(2, B_), 256>>>(out);
}

// round 5
// speedup vs baseline: 1.5211x; 1.5211x over previous
#include <cuda_runtime.h>

// Problem constants (fixed by the reference: B=32, d=512, T=2048)
#define B_  32
#define D_  512
#define T_  2048
#define FG  (4 * D_)        // 2048 G feature rows
#define FM  D_              // 512 m feature rows
#define FT  (FG + FM)       // 2560 total features
#define NSLICE 8
#define FS  (FT / NSLICE)   // 320 features per slice
#define TILE_T 512
#define THREADS 128         // each thread handles 4 consecutive t (float4)

// Partial dot-product scratch: [slice][b][t] per head. 2 MB each, 4 MB total.
__device__ float g_part1[NSLICE * B_ * T_];
__device__ float g_part2[NSLICE * B_ * T_];

__global__ __launch_bounds__(THREADS)
void dot_kernel(const float* __restrict__ G,
                const float* __restrict__ m1,
                const float* __restrict__ m2,
                const float* __restrict__ wp1,
                const float* __restrict__ wp2) {
    __shared__ float w1s[FS];
    __shared__ float w2s[FS];

    const int b     = blockIdx.y;
    const int slice = blockIdx.z;
    const int fbase = slice * FS;

    // Stage this slice's weights in shared memory (2.5 KB)
    for (int i = threadIdx.x; i < FS; i += THREADS) {
        w1s[i] = wp1[fbase + i];
        w2s[i] = wp2[fbase + i];
    }
    __syncthreads();

    const int t0 = blockIdx.x * TILE_T + threadIdx.x * 4;

    float a1x = 0.f, a1y = 0.f, a1z = 0.f, a1w = 0.f;
    float a2x = 0.f, a2y = 0.f, a2z = 0.f, a2w = 0.f;

    // --- G portion of this slice: f in [fbase, min(fbase+FS, FG)) ---
    const int fG_end = (fbase + FS < FG) ? (fbase + FS) : FG;
    const float* Gb = G + (size_t)b * FG * T_ + t0;
#pragma unroll 8
    for (int f = fbase; f < fG_end; ++f) {
        float4 g = *(const float4*)(Gb + (size_t)f * T_);
        float w1 = w1s[f - fbase];
        float w2 = w2s[f - fbase];
        a1x = fmaf(g.x, w1, a1x);  a2x = fmaf(g.x, w2, a2x);
        a1y = fmaf(g.y, w1, a1y);  a2y = fmaf(g.y, w2, a2y);
        a1z = fmaf(g.z, w1, a1z);  a2z = fmaf(g.z, w2, a2z);
        a1w = fmaf(g.w, w1, a1w);  a2w = fmaf(g.w, w2, a2w);
    }

    // --- m portion of this slice: f in [max(fbase, FG), fbase+FS) ---
    const int fM_beg = (fbase > FG) ? fbase : FG;
    const int fM_end = fbase + FS;
    const float* M1b = m1 + (size_t)b * FM * T_ + t0;
    const float* M2b = m2 + (size_t)b * FM * T_ + t0;
#pragma unroll 8
    for (int f = fM_beg; f < fM_end; ++f) {
        const int fm = f - FG;
        float4 v1 = *(const float4*)(M1b + (size_t)fm * T_);
        float4 v2 = *(const float4*)(M2b + (size_t)fm * T_);
        float w1 = w1s[f - fbase];
        float w2 = w2s[f - fbase];
        a1x = fmaf(v1.x, w1, a1x);  a2x = fmaf(v2.x, w2, a2x);
        a1y = fmaf(v1.y, w1, a1y);  a2y = fmaf(v2.y, w2, a2y);
        a1z = fmaf(v1.z, w1, a1z);  a2z = fmaf(v2.z, w2, a2z);
        a1w = fmaf(v1.w, w1, a1w);  a2w = fmaf(v2.w, w2, a2w);
    }

    const int o = (slice * B_ + b) * T_ + t0;
    *(float4*)&g_part1[o] = make_float4(a1x, a1y, a1z, a1w);
    *(float4*)&g_part2[o] = make_float4(a2x, a2y, a2z, a2w);
}

// Softmax over T for each (b, head). grid = (2 heads, B), 256 threads; each
// thread owns 8 t-values (stride-256 for coalescing). Sums the 8 f-slice
// partials on load.
__global__ __launch_bounds__(256)
void softmax_kernel(float* __restrict__ out) {
    const int head = blockIdx.x;
    const int b    = blockIdx.y;
    const float* P = (head == 0) ? g_part1 : g_part2;
    const int tid  = threadIdx.x;

    float p[8];
    float mx = -3.402823466e+38f;
#pragma unroll
    for (int i = 0; i < 8; ++i) {
        const int t = i * 256 + tid;
        float v = 0.f;
#pragma unroll
        for (int s = 0; s < NSLICE; ++s)
            v += P[(s * B_ + b) * T_ + t];
        p[i] = v;
        mx = fmaxf(mx, v);
    }

    __shared__ float red[256];
    red[tid] = mx;
    __syncthreads();
#pragma unroll
    for (int s = 128; s > 0; s >>= 1) {
        if (tid < s) red[tid] = fmaxf(red[tid], red[tid + s]);
        __syncthreads();
    }
    mx = red[0];
    __syncthreads();

    float sum = 0.f;
#pragma unroll
    for (int i = 0; i < 8; ++i) {
        p[i] = __expf(p[i] - mx);
        sum += p[i];
    }
    red[tid] = sum;
    __syncthreads();
#pragma unroll
    for (int s = 128; s > 0; s >>= 1) {
        if (tid < s) red[tid] += red[tid + s];
        __syncthreads();
    }
    const float inv = 1.0f / red[0];

#pragma unroll
    for (int i = 0; i < 8; ++i) {
        const int t = i * 256 + tid;
        out[((size_t)b * 2 + head) * T_ + t] = p[i] * inv;
    }
}

extern "C" void kernel_launch(void* const* d_in, const int* in_sizes, int n_in,
                              void* d_out, int out_size) {
    const float* G   = (const float*)d_in[0];
    const float* m1  = (const float*)d_in[1];
    const float* m2  = (const float*)d_in[2];
    const float* wp1 = (const float*)d_in[3];
    const float* wp2 = (const float*)d_in[4];
    float* out = (float*)d_out;

    dim3 grid(T_ / TILE_T, B_, NSLICE);   // (4, 32, 8) = 1024 blocks
    dot_kernel<<<grid, THREADS>>>(G, m1, m2, wp1, wp2);

    softmax_kernel<<<dim3(2, B_), 256>>>(out);
}

// round 6
// speedup vs baseline: 1.6949x; 1.1143x over previous
#include <cuda_runtime.h>

// Problem constants (fixed by the reference: B=32, d=512, T=2048)
#define B_  32
#define D_  512
#define T_  2048
#define FG  (4 * D_)        // 2048 G feature rows
#define FM  D_              // 512 m feature rows
#define FT  (FG + FM)       // 2560 total features
#define NSLICE 16
#define FS  (FT / NSLICE)   // 160 features per slice
#define TILE_T 1024         // 128 threads x 8 t each (two float4 chunks)
#define THREADS 128
#define HALF_T 512          // offset of second chunk

// Partial dot-product scratch: [slice][b][t] per head. 4 MB each, 8 MB total.
__device__ float g_part1[NSLICE * B_ * T_];
__device__ float g_part2[NSLICE * B_ * T_];

__global__ __launch_bounds__(THREADS)
void dot_kernel(const float* __restrict__ G,
                const float* __restrict__ m1,
                const float* __restrict__ m2,
                const float* __restrict__ wp1,
                const float* __restrict__ wp2) {
    __shared__ float w1s[FS];
    __shared__ float w2s[FS];

    const int b     = blockIdx.y;
    const int slice = blockIdx.z;
    const int fbase = slice * FS;

    for (int i = threadIdx.x; i < FS; i += THREADS) {
        w1s[i] = wp1[fbase + i];
        w2s[i] = wp2[fbase + i];
    }
    __syncthreads();

    // Two independent t-chunks per thread: t0 and t0 + HALF_T
    const int t0 = blockIdx.x * TILE_T + threadIdx.x * 4;

    // Accumulators: [head][chunk][lane]
    float a1ax=0.f,a1ay=0.f,a1az=0.f,a1aw=0.f, a1bx=0.f,a1by=0.f,a1bz=0.f,a1bw=0.f;
    float a2ax=0.f,a2ay=0.f,a2az=0.f,a2aw=0.f, a2bx=0.f,a2by=0.f,a2bz=0.f,a2bw=0.f;

    // --- G portion of this slice ---
    const int fG_end = (fbase + FS < FG) ? (fbase + FS) : FG;
    const float* Gb = G + (size_t)b * FG * T_ + t0;
#pragma unroll 4
    for (int f = fbase; f < fG_end; ++f) {
        const float* row = Gb + (size_t)f * T_;
        float4 ga = *(const float4*)(row);
        float4 gb = *(const float4*)(row + HALF_T);
        float w1 = w1s[f - fbase];
        float w2 = w2s[f - fbase];
        a1ax = fmaf(ga.x, w1, a1ax);  a2ax = fmaf(ga.x, w2, a2ax);
        a1ay = fmaf(ga.y, w1, a1ay);  a2ay = fmaf(ga.y, w2, a2ay);
        a1az = fmaf(ga.z, w1, a1az);  a2az = fmaf(ga.z, w2, a2az);
        a1aw = fmaf(ga.w, w1, a1aw);  a2aw = fmaf(ga.w, w2, a2aw);
        a1bx = fmaf(gb.x, w1, a1bx);  a2bx = fmaf(gb.x, w2, a2bx);
        a1by = fmaf(gb.y, w1, a1by);  a2by = fmaf(gb.y, w2, a2by);
        a1bz = fmaf(gb.z, w1, a1bz);  a2bz = fmaf(gb.z, w2, a2bz);
        a1bw = fmaf(gb.w, w1, a1bw);  a2bw = fmaf(gb.w, w2, a2bw);
    }

    // --- m portion of this slice ---
    const int fM_beg = (fbase > FG) ? fbase : FG;
    const int fM_end = fbase + FS;
    const float* M1b = m1 + (size_t)b * FM * T_ + t0;
    const float* M2b = m2 + (size_t)b * FM * T_ + t0;
#pragma unroll 4
    for (int f = fM_beg; f < fM_end; ++f) {
        const int fm = f - FG;
        const float* r1 = M1b + (size_t)fm * T_;
        const float* r2 = M2b + (size_t)fm * T_;
        float4 v1a = *(const float4*)(r1);
        float4 v1b = *(const float4*)(r1 + HALF_T);
        float4 v2a = *(const float4*)(r2);
        float4 v2b = *(const float4*)(r2 + HALF_T);
        float w1 = w1s[f - fbase];
        float w2 = w2s[f - fbase];
        a1ax = fmaf(v1a.x, w1, a1ax);  a2ax = fmaf(v2a.x, w2, a2ax);
        a1ay = fmaf(v1a.y, w1, a1ay);  a2ay = fmaf(v2a.y, w2, a2ay);
        a1az = fmaf(v1a.z, w1, a1az);  a2az = fmaf(v2a.z, w2, a2az);
        a1aw = fmaf(v1a.w, w1, a1aw);  a2aw = fmaf(v2a.w, w2, a2aw);
        a1bx = fmaf(v1b.x, w1, a1bx);  a2bx = fmaf(v2b.x, w2, a2bx);
        a1by = fmaf(v1b.y, w1, a1by);  a2by = fmaf(v2b.y, w2, a2by);
        a1bz = fmaf(v1b.z, w1, a1bz);  a2bz = fmaf(v2b.z, w2, a2bz);
        a1bw = fmaf(v1b.w, w1, a1bw);  a2bw = fmaf(v2b.w, w2, a2bw);
    }

    const int o = (slice * B_ + b) * T_ + t0;
    *(float4*)&g_part1[o]          = make_float4(a1ax, a1ay, a1az, a1aw);
    *(float4*)&g_part1[o + HALF_T] = make_float4(a1bx, a1by, a1bz, a1bw);
    *(float4*)&g_part2[o]          = make_float4(a2ax, a2ay, a2az, a2aw);
    *(float4*)&g_part2[o + HALF_T] = make_float4(a2bx, a2by, a2bz, a2bw);
}

// Softmax over T for each (b, head). grid = (2 heads, B), 256 threads; each
// thread owns 8 t-values (stride-256). Sums the 16 f-slice partials on load.
__global__ __launch_bounds__(256)
void softmax_kernel(float* __restrict__ out) {
    const int head = blockIdx.x;
    const int b    = blockIdx.y;
    const float* P = (head == 0) ? g_part1 : g_part2;
    const int tid  = threadIdx.x;

    float p[8];
    float mx = -3.402823466e+38f;
#pragma unroll
    for (int i = 0; i < 8; ++i) {
        const int t = i * 256 + tid;
        float v = 0.f;
#pragma unroll
        for (int s = 0; s < NSLICE; ++s)
            v += P[(s * B_ + b) * T_ + t];
        p[i] = v;
        mx = fmaxf(mx, v);
    }

    __shared__ float red[256];
    red[tid] = mx;
    __syncthreads();
#pragma unroll
    for (int s = 128; s > 0; s >>= 1) {
        if (tid < s) red[tid] = fmaxf(red[tid], red[tid + s]);
        __syncthreads();
    }
    mx = red[0];
    __syncthreads();

    float sum = 0.f;
#pragma unroll
    for (int i = 0; i < 8; ++i) {
        p[i] = __expf(p[i] - mx);
        sum += p[i];
    }
    red[tid] = sum;
    __syncthreads();
#pragma unroll
    for (int s = 128; s > 0; s >>= 1) {
        if (tid < s) red[tid] += red[tid + s];
        __syncthreads();
    }
    const float inv = 1.0f / red[0];

#pragma unroll
    for (int i = 0; i < 8; ++i) {
        const int t = i * 256 + tid;
        out[((size_t)b * 2 + head) * T_ + t] = p[i] * inv;
    }
}

extern "C" void kernel_launch(void* const* d_in, const int* in_sizes, int n_in,
                              void* d_out, int out_size) {
    const float* G   = (const float*)d_in[0];
    const float* m1  = (const float*)d_in[1];
    const float* m2  = (const float*)d_in[2];
    const float* wp1 = (const float*)d_in[3];
    const float* wp2 = (const float*)d_in[4];
    float* out = (float*)d_out;

    dim3 grid(T_ / TILE_T, B_, NSLICE);   // (2, 32, 16) = 1024 blocks
    dot_kernel<<<grid, THREADS>>>(G, m1, m2, wp1, wp2);

    softmax_kernel<<<dim3(2, B_), 256>>>(out);
}

// round 8
// speedup vs baseline: 2.1867x; 1.2902x over previous
#include <cuda_runtime.h>

// Problem constants (fixed by the reference: B=32, d=512, T=2048)
#define B_  32
#define D_  512
#define T_  2048
#define FG  (4 * D_)        // 2048 G feature rows
#define FM  D_              // 512 m feature rows
#define FT  (FG + FM)       // 2560 total features
#define NSLICE 16
#define FS  (FT / NSLICE)   // 160 features per slice
#define TILE_T 1024         // 128 threads x 8 t each (two float4 chunks)
#define THREADS 128
#define HALF_T 512          // offset of second chunk

// Partial dot-product scratch: [slice][b][t] per head. 4 MB each, 8 MB total.
__device__ float g_part1[NSLICE * B_ * T_];
__device__ float g_part2[NSLICE * B_ * T_];

// min-blocks=8 forces <=64 regs/thread -> 8 CTAs/SM -> all 1024 blocks
// resident in a single wave (no tail wave).
__global__ __launch_bounds__(THREADS, 8)
void dot_kernel(const float* __restrict__ G,
                const float* __restrict__ m1,
                const float* __restrict__ m2,
                const float* __restrict__ wp1,
                const float* __restrict__ wp2) {
    __shared__ float w1s[FS];
    __shared__ float w2s[FS];

    const int b     = blockIdx.y;
    const int slice = blockIdx.z;
    const int fbase = slice * FS;

    for (int i = threadIdx.x; i < FS; i += THREADS) {
        w1s[i] = wp1[fbase + i];
        w2s[i] = wp2[fbase + i];
    }
    __syncthreads();

    // Two independent t-chunks per thread: t0 and t0 + HALF_T
    const int t0 = blockIdx.x * TILE_T + threadIdx.x * 4;

    float a1ax=0.f,a1ay=0.f,a1az=0.f,a1aw=0.f, a1bx=0.f,a1by=0.f,a1bz=0.f,a1bw=0.f;
    float a2ax=0.f,a2ay=0.f,a2az=0.f,a2aw=0.f, a2bx=0.f,a2by=0.f,a2bz=0.f,a2bw=0.f;

    // --- G portion of this slice ---
    const int fG_end = (fbase + FS < FG) ? (fbase + FS) : FG;
    const float* Gb = G + (size_t)b * FG * T_ + t0;
#pragma unroll 4
    for (int f = fbase; f < fG_end; ++f) {
        const float* row = Gb + (size_t)f * T_;
        float4 ga = __ldcs((const float4*)(row));
        float4 gb = __ldcs((const float4*)(row + HALF_T));
        float w1 = w1s[f - fbase];
        float w2 = w2s[f - fbase];
        a1ax = fmaf(ga.x, w1, a1ax);  a2ax = fmaf(ga.x, w2, a2ax);
        a1ay = fmaf(ga.y, w1, a1ay);  a2ay = fmaf(ga.y, w2, a2ay);
        a1az = fmaf(ga.z, w1, a1az);  a2az = fmaf(ga.z, w2, a2az);
        a1aw = fmaf(ga.w, w1, a1aw);  a2aw = fmaf(ga.w, w2, a2aw);
        a1bx = fmaf(gb.x, w1, a1bx);  a2bx = fmaf(gb.x, w2, a2bx);
        a1by = fmaf(gb.y, w1, a1by);  a2by = fmaf(gb.y, w2, a2by);
        a1bz = fmaf(gb.z, w1, a1bz);  a2bz = fmaf(gb.z, w2, a2bz);
        a1bw = fmaf(gb.w, w1, a1bw);  a2bw = fmaf(gb.w, w2, a2bw);
    }

    // --- m portion of this slice ---
    const int fM_beg = (fbase > FG) ? fbase : FG;
    const int fM_end = fbase + FS;
    const float* M1b = m1 + (size_t)b * FM * T_ + t0;
    const float* M2b = m2 + (size_t)b * FM * T_ + t0;
#pragma unroll 4
    for (int f = fM_beg; f < fM_end; ++f) {
        const int fm = f - FG;
        const float* r1 = M1b + (size_t)fm * T_;
        const float* r2 = M2b + (size_t)fm * T_;
        float4 v1a = __ldcs((const float4*)(r1));
        float4 v1b = __ldcs((const float4*)(r1 + HALF_T));
        float4 v2a = __ldcs((const float4*)(r2));
        float4 v2b = __ldcs((const float4*)(r2 + HALF_T));
        float w1 = w1s[f - fbase];
        float w2 = w2s[f - fbase];
        a1ax = fmaf(v1a.x, w1, a1ax);  a2ax = fmaf(v2a.x, w2, a2ax);
        a1ay = fmaf(v1a.y, w1, a1ay);  a2ay = fmaf(v2a.y, w2, a2ay);
        a1az = fmaf(v1a.z, w1, a1az);  a2az = fmaf(v2a.z, w2, a2az);
        a1aw = fmaf(v1a.w, w1, a1aw);  a2aw = fmaf(v2a.w, w2, a2aw);
        a1bx = fmaf(v1b.x, w1, a1bx);  a2bx = fmaf(v2b.x, w2, a2bx);
        a1by = fmaf(v1b.y, w1, a1by);  a2by = fmaf(v2b.y, w2, a2by);
        a1bz = fmaf(v1b.z, w1, a1bz);  a2bz = fmaf(v2b.z, w2, a2bz);
        a1bw = fmaf(v1b.w, w1, a1bw);  a2bw = fmaf(v2b.w, w2, a2bw);
    }

    const int o = (slice * B_ + b) * T_ + t0;
    *(float4*)&g_part1[o]          = make_float4(a1ax, a1ay, a1az, a1aw);
    *(float4*)&g_part1[o + HALF_T] = make_float4(a1bx, a1by, a1bz, a1bw);
    *(float4*)&g_part2[o]          = make_float4(a2ax, a2ay, a2az, a2aw);
    *(float4*)&g_part2[o + HALF_T] = make_float4(a2bx, a2by, a2bz, a2bw);
}

// Softmax over T for each (b, head). grid = (2 heads, B), 512 threads; each
// thread owns 4 consecutive t (one float4 per slice -> 16 independent loads).
// Warp-shuffle + smem reductions.
__global__ __launch_bounds__(512)
void softmax_kernel(float* __restrict__ out) {
    const int head = blockIdx.x;
    const int b    = blockIdx.y;
    const float* P = (head == 0) ? g_part1 : g_part2;
    const int tid  = threadIdx.x;
    const int t0   = tid * 4;

    float vx = 0.f, vy = 0.f, vz = 0.f, vw = 0.f;
#pragma unroll
    for (int s = 0; s < NSLICE; ++s) {
        float4 q = *(const float4*)&P[(s * B_ + b) * T_ + t0];
        vx += q.x; vy += q.y; vz += q.z; vw += q.w;
    }

    // --- block max ---
    float mx = fmaxf(fmaxf(vx, vy), fmaxf(vz, vw));
#pragma unroll
    for (int o = 16; o > 0; o >>= 1)
        mx = fmaxf(mx, __shfl_xor_sync(0xffffffffu, mx, o));
    __shared__ float red[16];
    const int wid = tid >> 5, lid = tid & 31;
    if (lid == 0) red[wid] = mx;
    __syncthreads();
    if (wid == 0) {
        float r = red[lid & 15];
#pragma unroll
        for (int o = 8; o > 0; o >>= 1)
            r = fmaxf(r, __shfl_xor_sync(0xffffffffu, r, o));
        if (lid == 0) red[0] = r;
    }
    __syncthreads();
    mx = red[0];
    __syncthreads();

    // --- exp + block sum ---
    vx = __expf(vx - mx); vy = __expf(vy - mx);
    vz = __expf(vz - mx); vw = __expf(vw - mx);
    float sum = vx + vy + vz + vw;
#pragma unroll
    for (int o = 16; o > 0; o >>= 1)
        sum += __shfl_xor_sync(0xffffffffu, sum, o);
    if (lid == 0) red[wid] = sum;
    __syncthreads();
    if (wid == 0) {
        float r = red[lid & 15];
#pragma unroll
        for (int o = 8; o > 0; o >>= 1)
            r += __shfl_xor_sync(0xffffffffu, r, o);
        if (lid == 0) red[0] = r;
    }
    __syncthreads();
    const float inv = 1.0f / red[0];

    float4 res = make_float4(vx * inv, vy * inv, vz * inv, vw * inv);
    *(float4*)&out[((size_t)b * 2 + head) * T_ + t0] = res;
}

extern "C" void kernel_launch(void* const* d_in, const int* in_sizes, int n_in,
                              void* d_out, int out_size) {
    const float* G   = (const float*)d_in[0];
    const float* m1  = (const float*)d_in[1];
    const float* m2  = (const float*)d_in[2];
    const float* wp1 = (const float*)d_in[3];
    const float* wp2 = (const float*)d_in[4];
    float* out = (float*)d_out;

    dim3 grid(T_ / TILE_T, B_, NSLICE);   // (2, 32, 16) = 1024 blocks
    dot_kernel<<<grid, THREADS>>>(G, m1, m2, wp1, wp2);

    softmax_kernel<<<dim3(2, B_), 512>>>(out);
}